// round 2
// baseline (speedup 1.0000x reference)
#include <cuda_runtime.h>
#include <math.h>

// Problem constants (fixed by the reference: B=8, N=48, D=2)
#define BB 8
#define NN 48
#define MM (NN * NN)          // 2304 vectors per batch
#define BLOCKS_PER_BATCH 64
#define PAIR_BLOCKS (BB * BLOCKS_PER_BATCH)   // 512
#define CTHREADS 256

// Scratch (no allocations allowed -> __device__ globals)
__device__ float2 g_u[BB * MM];      // compacted normalized vectors per batch
__device__ int    g_cnt[BB];         // nonzero count per batch
__device__ float  g_part[PAIR_BLOCKS];

// ---------------------------------------------------------------------------
// Kernel 1: per-batch compaction. 8 blocks x 256 threads.
// Deterministic (stable block-wide scan, fixed iteration order).
// ---------------------------------------------------------------------------
__global__ void compact_kernel(const float* __restrict__ gt,
                               const float* __restrict__ cs,
                               const float* __restrict__ thr) {
    const int b   = blockIdx.x;
    const int tid = threadIdx.x;
    const int lane = tid & 31;
    const int wid  = tid >> 5;

    __shared__ float sgx[NN], sgy[NN];
    __shared__ int warp_tot[8];
    __shared__ int s_base;

    if (tid < NN) {
        sgx[tid] = gt[(b * NN + tid) * 2 + 0];
        sgy[tid] = gt[(b * NN + tid) * 2 + 1];
    }
    if (tid == 0) s_base = 0;
    __syncthreads();

    const float t = thr[0];

    for (int base = 0; base < MM; base += CTHREADS) {
        int idx = base + tid;
        float ux = 0.f, uy = 0.f;
        int flag = 0;
        if (idx < MM) {
            int i = idx / NN;
            int j = idx - i * NN;
            float s = cs[b * MM + idx];
            if (s >= t) {   // reference: where(cos < thr, 0, cos)
                float vx = (sgx[i] - sgx[j]) * s;
                float vy = (sgy[i] - sgy[j]) * s;
                if (vx != 0.f || vy != 0.f) {
                    flag = 1;
                    // per-element eps: sqrt(vx^2 + eps + vy^2 + eps)
                    float vabs = sqrtf(vx * vx + 1e-9f + vy * vy + 1e-9f);
                    float inv = 1.0f / vabs;
                    ux = vx * inv;
                    uy = vy * inv;
                }
            }
        }
        // stable block scan of flags
        unsigned bal = __ballot_sync(0xffffffffu, flag);
        int pre    = __popc(bal & ((1u << lane) - 1u));
        int wcount = __popc(bal);
        if (lane == 0) warp_tot[wid] = wcount;
        __syncthreads();
        int woff = 0;
        #pragma unroll
        for (int w = 0; w < 8; w++) if (w < wid) woff += warp_tot[w];
        int total = 0;
        #pragma unroll
        for (int w = 0; w < 8; w++) total += warp_tot[w];
        if (flag) {
            int pos = s_base + woff + pre;
            g_u[b * MM + pos] = make_float2(ux, uy);
        }
        __syncthreads();
        if (tid == 0) s_base += total;
        __syncthreads();
    }
    if (tid == 0) g_cnt[b] = s_base;
}

// ---------------------------------------------------------------------------
// Kernel 2: all-pairs |u_m . u_n| per batch. 512 blocks x 256 threads.
// Each block handles batch b = blockIdx.x / 64, m-rows strided by 64.
// Vectors cached in shared memory. Deterministic partial-sum slots.
// ---------------------------------------------------------------------------
__global__ void pair_kernel() {
    const int b   = blockIdx.x / BLOCKS_PER_BATCH;
    const int sub = blockIdx.x % BLOCKS_PER_BATCH;
    const int tid = threadIdx.x;
    const int K   = g_cnt[b];

    __shared__ float2 su[MM];
    for (int i = tid; i < K; i += CTHREADS) su[i] = g_u[b * MM + i];
    __syncthreads();

    float acc = 0.f;
    for (int m = sub; m < K; m += BLOCKS_PER_BATCH) {
        float2 um = su[m];
        for (int n = tid; n < K; n += CTHREADS) {
            float2 un = su[n];
            acc += fabsf(um.x * un.x + um.y * un.y);
        }
    }

    __shared__ float red[CTHREADS];
    red[tid] = acc;
    __syncthreads();
    #pragma unroll
    for (int s = CTHREADS / 2; s > 0; s >>= 1) {
        if (tid < s) red[tid] += red[tid + s];
        __syncthreads();
    }
    if (tid == 0) g_part[blockIdx.x] = red[0];
}

// ---------------------------------------------------------------------------
// Kernel 3: final reduce (fixed order), idx_num = sum K_b^2, divide.
// ---------------------------------------------------------------------------
__global__ void final_kernel(float* __restrict__ out) {
    const int tid = threadIdx.x;
    __shared__ float red[PAIR_BLOCKS];
    red[tid] = g_part[tid];
    __syncthreads();
    #pragma unroll
    for (int s = PAIR_BLOCKS / 2; s > 0; s >>= 1) {
        if (tid < s) red[tid] += red[tid + s];
        __syncthreads();
    }
    if (tid == 0) {
        double idx_num = 0.0;
        #pragma unroll
        for (int b = 0; b < BB; b++) {
            double k = (double)g_cnt[b];
            idx_num += k * k;
        }
        out[0] = (float)((double)red[0] / idx_num);
    }
}

extern "C" void kernel_launch(void* const* d_in, const int* in_sizes, int n_in,
                              void* d_out, int out_size) {
    const float* gt  = (const float*)d_in[0];   // [8,48,2]
    const float* cs  = (const float*)d_in[1];   // [8,48,48]
    const float* thr = (const float*)d_in[2];   // [1]
    float* out = (float*)d_out;

    compact_kernel<<<BB, CTHREADS>>>(gt, cs, thr);
    pair_kernel<<<PAIR_BLOCKS, CTHREADS>>>();
    final_kernel<<<1, PAIR_BLOCKS>>>(out);
}

// round 3
// speedup vs baseline: 1.1688x; 1.1688x over previous
#include <cuda_runtime.h>
#include <math.h>

// Fixed problem shape: B=8, N=48, D=2
#define BB 8
#define NN 48
#define MM (NN * NN)        // 2304 candidate vectors per batch
#define CHUNKS 9            // MM / 256
#define BPB 64              // blocks per batch
#define GRID (BB * BPB)     // 512
#define T 256               // threads per block

// Scratch (allocations forbidden -> device globals)
__device__ float g_part[GRID];
__device__ int   g_cnt[BB];

// ---------------------------------------------------------------------------
// Fused kernel: each block (re)compacts its batch's nonzero normalized pair
// vectors into shared memory (deterministic fixed order), then accumulates
// 2 * sum_{m<n} |u_m . u_n| over its strided row slice.
// ---------------------------------------------------------------------------
__global__ __launch_bounds__(T) void fused_kernel(const float* __restrict__ gt,
                                                  const float* __restrict__ cs,
                                                  const float* __restrict__ thr) {
    const int b    = blockIdx.x >> 6;      // batch
    const int sub  = blockIdx.x & (BPB - 1);
    const int tid  = threadIdx.x;
    const int lane = tid & 31;
    const int wid  = tid >> 5;

    __shared__ float2 sg[NN];      // gt points for this batch
    __shared__ float2 su[MM];      // compacted unit vectors
    __shared__ int    warp_tot[8];
    __shared__ float  red[T];

    if (tid < NN) sg[tid] = ((const float2*)gt)[b * NN + tid];

    // Prefetch all similarity values for this thread (MLP=9, one round trip)
    float s[CHUNKS];
    #pragma unroll
    for (int k = 0; k < CHUNKS; k++) s[k] = cs[b * MM + k * T + tid];
    const float t = thr[0];
    __syncthreads();

    // Compute normalized vectors + flags, all in registers
    float2 u[CHUNKS];
    int    flag[CHUNKS];
    int cnt = 0;
    #pragma unroll
    for (int k = 0; k < CHUNKS; k++) {
        int idx = k * T + tid;
        int i = idx / NN;
        int j = idx - i * NN;
        float ss = s[k];
        float vx = 0.f, vy = 0.f;
        int f = 0;
        if (ss >= t) {                       // ref: where(cos < thr, 0, cos)
            vx = (sg[i].x - sg[j].x) * ss;
            vy = (sg[i].y - sg[j].y) * ss;
            if (vx != 0.f || vy != 0.f) f = 1;
        }
        if (f) {
            // per-element eps as in reference: sqrt(vx^2+eps + vy^2+eps)
            float inv = rsqrtf(vx * vx + 1e-9f + vy * vy + 1e-9f);
            u[k] = make_float2(vx * inv, vy * inv);
        } else {
            u[k] = make_float2(0.f, 0.f);
        }
        flag[k] = f;
        cnt += f;
    }

    // Single block-wide exclusive scan of per-thread counts (deterministic)
    int inc = cnt;
    #pragma unroll
    for (int d = 1; d < 32; d <<= 1) {
        int v = __shfl_up_sync(0xffffffffu, inc, d);
        if (lane >= d) inc += v;
    }
    if (lane == 31) warp_tot[wid] = inc;
    __syncthreads();
    int wbase = 0, K = 0;
    #pragma unroll
    for (int w = 0; w < 8; w++) {
        int wt = warp_tot[w];
        if (w < wid) wbase += wt;
        K += wt;
    }
    int pos = wbase + inc - cnt;   // exclusive prefix for this thread

    // Scatter compacted vectors (fixed per-run order: (tid, k) lexicographic)
    #pragma unroll
    for (int k = 0; k < CHUNKS; k++) {
        if (flag[k]) su[pos++] = u[k];
    }
    __syncthreads();

    // Upper-triangle pair sum over strided rows
    float acc = 0.f;
    for (int m = sub; m < K; m += BPB) {
        float2 um = su[m];          // broadcast
        for (int n = m + 1 + tid; n < K; n += T) {
            float2 un = su[n];
            acc += fabsf(um.x * un.x + um.y * un.y);
        }
    }

    // Block reduction (fixed order)
    red[tid] = acc;
    __syncthreads();
    #pragma unroll
    for (int sft = T / 2; sft > 0; sft >>= 1) {
        if (tid < sft) red[tid] += red[tid + sft];
        __syncthreads();
    }
    if (tid == 0) {
        g_part[blockIdx.x] = red[0];
        if (sub == 0) g_cnt[b] = K;
    }
}

// ---------------------------------------------------------------------------
// Final: total = sum(2*partials) + sum_b K_b (diagonal), / idx_num = sum K_b^2
// ---------------------------------------------------------------------------
__global__ __launch_bounds__(GRID) void final_kernel(float* __restrict__ out) {
    const int tid = threadIdx.x;
    __shared__ float red[GRID];
    red[tid] = g_part[tid];
    __syncthreads();
    #pragma unroll
    for (int sft = GRID / 2; sft > 0; sft >>= 1) {
        if (tid < sft) red[tid] += red[tid + sft];
        __syncthreads();
    }
    if (tid == 0) {
        double diag = 0.0, idx_num = 0.0;
        #pragma unroll
        for (int b = 0; b < BB; b++) {
            double k = (double)g_cnt[b];
            diag += k;
            idx_num += k * k;
        }
        double total = 2.0 * (double)red[0] + diag;
        out[0] = (float)(total / idx_num);
    }
}

extern "C" void kernel_launch(void* const* d_in, const int* in_sizes, int n_in,
                              void* d_out, int out_size) {
    const float* gt  = (const float*)d_in[0];   // [8,48,2]
    const float* cs  = (const float*)d_in[1];   // [8,48,48]
    const float* thr = (const float*)d_in[2];   // [1]
    float* out = (float*)d_out;

    fused_kernel<<<GRID, T>>>(gt, cs, thr);
    final_kernel<<<1, GRID>>>(out);
}

// round 4
// speedup vs baseline: 1.3846x; 1.1846x over previous
#include <cuda_runtime.h>
#include <math.h>

// Fixed problem shape: B=8, N=48, D=2
#define BB 8
#define NN 48
#define MM (NN * NN)        // 2304 candidate vectors per batch (= 9*256)
#define CHUNKS 9            // MM / 256
#define BPB 64              // blocks per batch
#define GRID (BB * BPB)     // 512
#define T 256               // threads per block

// Scratch (allocations forbidden -> device globals)
__device__ float g_part[GRID];
__device__ int   g_cnt[BB];
__device__ int   g_ticket = 0;

__global__ __launch_bounds__(T) void fused_kernel(const float* __restrict__ gt,
                                                  const float* __restrict__ cs,
                                                  const float* __restrict__ thr,
                                                  float* __restrict__ out) {
    const int b    = blockIdx.x >> 6;      // batch
    const int sub  = blockIdx.x & (BPB - 1);
    const int tid  = threadIdx.x;
    const int lane = tid & 31;
    const int wid  = tid >> 5;

    __shared__ float2 sg[NN];       // gt points for this batch
    __shared__ float2 su[MM];       // compacted unit vectors (zero padded)
    __shared__ int    warp_tot[8];
    __shared__ float  warp_sum[8];
    __shared__ float  red[T];
    __shared__ bool   s_last;

    if (tid < NN) sg[tid] = ((const float2*)gt)[b * NN + tid];

    // Prefetch all similarity values for this thread (MLP=9, one round trip)
    float s[CHUNKS];
    #pragma unroll
    for (int k = 0; k < CHUNKS; k++) s[k] = cs[b * MM + k * T + tid];
    const float t = thr[0];
    __syncthreads();

    // ---- compute normalized vectors + flags in registers ----
    float2 u[CHUNKS];
    int    flag[CHUNKS];
    int cnt = 0;
    #pragma unroll
    for (int k = 0; k < CHUNKS; k++) {
        int idx = k * T + tid;
        int i = idx / NN;
        int j = idx - i * NN;
        float ss = s[k];
        float vx = 0.f, vy = 0.f;
        int f = 0;
        if (ss >= t) {                       // ref: where(cos < thr, 0, cos)
            vx = (sg[i].x - sg[j].x) * ss;
            vy = (sg[i].y - sg[j].y) * ss;
            if (vx != 0.f || vy != 0.f) f = 1;
        }
        if (f) {
            // per-element eps as in reference: sqrt(vx^2+eps + vy^2+eps)
            float inv = rsqrtf(vx * vx + 1e-9f + vy * vy + 1e-9f);
            u[k] = make_float2(vx * inv, vy * inv);
        } else {
            u[k] = make_float2(0.f, 0.f);
        }
        flag[k] = f;
        cnt += f;
    }

    // ---- block-wide exclusive scan of per-thread counts (deterministic) ----
    int inc = cnt;
    #pragma unroll
    for (int d = 1; d < 32; d <<= 1) {
        int v = __shfl_up_sync(0xffffffffu, inc, d);
        if (lane >= d) inc += v;
    }
    if (lane == 31) warp_tot[wid] = inc;
    __syncthreads();
    int wbase = 0, K = 0;
    #pragma unroll
    for (int w = 0; w < 8; w++) {
        int wt = warp_tot[w];
        if (w < wid) wbase += wt;
        K += wt;
    }
    int pos = wbase + inc - cnt;   // exclusive prefix for this thread

    // ---- scatter compacted vectors (fixed order), zero-pad the rest ----
    #pragma unroll
    for (int k = 0; k < CHUNKS; k++) {
        if (flag[k]) su[pos++] = u[k];
    }
    for (int i = K + tid; i < MM; i += T) su[i] = make_float2(0.f, 0.f);
    __syncthreads();

    // ---- pair phase: columns in registers, rows via broadcast LDS ----
    float2 un[CHUNKS];
    #pragma unroll
    for (int c = 0; c < CHUNKS; c++) un[c] = su[c * T + tid];

    float acc = 0.f;
    for (int m = sub; m < K; m += BPB) {
        float2 um = su[m];          // warp broadcast
        #pragma unroll
        for (int c = 0; c < CHUNKS; c++) {
            acc += fabsf(um.x * un[c].x + um.y * un[c].y);
        }
    }

    // ---- block reduction: warp shuffle tree, fixed order ----
    #pragma unroll
    for (int d = 16; d > 0; d >>= 1)
        acc += __shfl_xor_sync(0xffffffffu, acc, d);
    if (lane == 0) warp_sum[wid] = acc;
    __syncthreads();
    if (tid == 0) {
        float bs = 0.f;
        #pragma unroll
        for (int w = 0; w < 8; w++) bs += warp_sum[w];
        g_part[blockIdx.x] = bs;
        if (sub == 0) g_cnt[b] = K;
        __threadfence();
        int ticket = atomicAdd(&g_ticket, 1);
        s_last = (ticket == GRID - 1);
    }
    __syncthreads();

    // ---- last block finishes: reduce 512 partials in fixed order ----
    if (s_last) {
        __threadfence();
        red[tid] = g_part[tid] + g_part[tid + T];
        __syncthreads();
        #pragma unroll
        for (int sft = T / 2; sft > 0; sft >>= 1) {
            if (tid < sft) red[tid] += red[tid + sft];
            __syncthreads();
        }
        if (tid == 0) {
            double idx_num = 0.0;
            #pragma unroll
            for (int bb = 0; bb < BB; bb++) {
                double k = (double)g_cnt[bb];
                idx_num += k * k;
            }
            out[0] = (float)((double)red[0] / idx_num);
            g_ticket = 0;    // reset for next graph replay
        }
    }
}

extern "C" void kernel_launch(void* const* d_in, const int* in_sizes, int n_in,
                              void* d_out, int out_size) {
    const float* gt  = (const float*)d_in[0];   // [8,48,2]
    const float* cs  = (const float*)d_in[1];   // [8,48,48]
    const float* thr = (const float*)d_in[2];   // [1]
    float* out = (float*)d_out;

    fused_kernel<<<GRID, T>>>(gt, cs, thr, out);
}

// round 5
// speedup vs baseline: 1.5829x; 1.1432x over previous
#include <cuda_runtime.h>
#include <math.h>

// Fixed problem shape: B=8, N=48, D=2
#define BB 8
#define NN 48
#define MM (NN * NN)        // 2304 candidate vectors per batch (= 9*256)
#define CHUNKS 9            // MM / 256
#define BPB 37              // blocks per batch -> GRID = 296 = 2 blocks/SM on 148 SMs
#define GRID (BB * BPB)
#define T 256               // threads per block

// Scratch (allocations forbidden -> device globals)
__device__ float g_part[GRID];
__device__ int   g_cnt[BB];
__device__ int   g_ticket = 0;

// Pair-phase sum for a block: NF full column-chunks (all 256 lanes valid) in
// registers, plus one boundary chunk for lanes with NF*256+tid < K.
// K < (NF+1)*256 is guaranteed by the dispatch (NF = K >> 8).
template <int NF>
__device__ __forceinline__ float pair_sum(const float2* __restrict__ su,
                                          int K, int sub, int tid) {
    float2 un[NF > 0 ? NF : 1];
#pragma unroll
    for (int c = 0; c < NF; c++) un[c] = su[c * T + tid];

    float a0 = 0.f, a1 = 0.f;
    if (NF > 0) {
        int m = sub;
        for (; m + BPB < K; m += 2 * BPB) {
            float2 um0 = su[m];
            float2 um1 = su[m + BPB];
#pragma unroll
            for (int c = 0; c < NF; c++) {
                a0 += fabsf(um0.x * un[c].x + um0.y * un[c].y);
                a1 += fabsf(um1.x * un[c].x + um1.y * un[c].y);
            }
        }
        if (m < K) {
            float2 um = su[m];
#pragma unroll
            for (int c = 0; c < NF; c++)
                a0 += fabsf(um.x * un[c].x + um.y * un[c].y);
        }
    }

    // boundary chunk (only lanes with a valid column; whole warps skip)
    int cidx = NF * T + tid;
    if (cidx < K) {
        float2 ub = su[cidx];
        float b0 = 0.f, b1 = 0.f;
        int m = sub;
        for (; m + BPB < K; m += 2 * BPB) {
            float2 um0 = su[m];
            float2 um1 = su[m + BPB];
            b0 += fabsf(um0.x * ub.x + um0.y * ub.y);
            b1 += fabsf(um1.x * ub.x + um1.y * ub.y);
        }
        if (m < K) {
            float2 um = su[m];
            b0 += fabsf(um.x * ub.x + um.y * ub.y);
        }
        a0 += b0 + b1;
    }
    return a0 + a1;
}

__global__ __launch_bounds__(T) void fused_kernel(const float* __restrict__ gt,
                                                  const float* __restrict__ cs,
                                                  const float* __restrict__ thr,
                                                  float* __restrict__ out) {
    const int b    = blockIdx.x / BPB;
    const int sub  = blockIdx.x - b * BPB;
    const int tid  = threadIdx.x;
    const int lane = tid & 31;
    const int wid  = tid >> 5;

    __shared__ float2 sg[NN];       // gt points for this batch
    __shared__ float2 su[MM];       // compacted unit vectors
    __shared__ int    warp_tot[8];
    __shared__ float  warp_sum[8];
    __shared__ float  red[T];
    __shared__ bool   s_last;

    if (tid < NN) sg[tid] = ((const float2*)gt)[b * NN + tid];

    // Prefetch all similarity values for this thread (MLP=9, one round trip)
    float s[CHUNKS];
#pragma unroll
    for (int k = 0; k < CHUNKS; k++) s[k] = cs[b * MM + k * T + tid];
    const float t = thr[0];
    __syncthreads();

    // ---- compute normalized vectors + flags in registers ----
    float2 u[CHUNKS];
    int    flag[CHUNKS];
    int cnt = 0;
#pragma unroll
    for (int k = 0; k < CHUNKS; k++) {
        int idx = k * T + tid;
        int i = idx / NN;
        int j = idx - i * NN;
        float ss = s[k];
        float vx = 0.f, vy = 0.f;
        int f = 0;
        if (ss >= t) {                       // ref: where(cos < thr, 0, cos)
            vx = (sg[i].x - sg[j].x) * ss;
            vy = (sg[i].y - sg[j].y) * ss;
            if (vx != 0.f || vy != 0.f) f = 1;
        }
        if (f) {
            // per-element eps as in reference: sqrt(vx^2+eps + vy^2+eps)
            float inv = rsqrtf(vx * vx + 1e-9f + vy * vy + 1e-9f);
            u[k] = make_float2(vx * inv, vy * inv);
        } else {
            u[k] = make_float2(0.f, 0.f);
        }
        flag[k] = f;
        cnt += f;
    }

    // ---- block-wide exclusive scan of per-thread counts (deterministic) ----
    int inc = cnt;
#pragma unroll
    for (int d = 1; d < 32; d <<= 1) {
        int v = __shfl_up_sync(0xffffffffu, inc, d);
        if (lane >= d) inc += v;
    }
    if (lane == 31) warp_tot[wid] = inc;
    __syncthreads();
    int wbase = 0, K = 0;
#pragma unroll
    for (int w = 0; w < 8; w++) {
        int wt = warp_tot[w];
        if (w < wid) wbase += wt;
        K += wt;
    }
    int pos = wbase + inc - cnt;   // exclusive prefix for this thread

    // ---- scatter compacted vectors (fixed order), no padding needed ----
#pragma unroll
    for (int k = 0; k < CHUNKS; k++) {
        if (flag[k]) su[pos++] = u[k];
    }
    __syncthreads();

    // ---- pair phase: dispatch on number of full 256-wide chunks ----
    float acc;
    switch (K >> 8) {
        case 0: acc = pair_sum<0>(su, K, sub, tid); break;
        case 1: acc = pair_sum<1>(su, K, sub, tid); break;
        case 2: acc = pair_sum<2>(su, K, sub, tid); break;
        case 3: acc = pair_sum<3>(su, K, sub, tid); break;
        case 4: acc = pair_sum<4>(su, K, sub, tid); break;
        case 5: acc = pair_sum<5>(su, K, sub, tid); break;
        case 6: acc = pair_sum<6>(su, K, sub, tid); break;
        case 7: acc = pair_sum<7>(su, K, sub, tid); break;
        default: acc = pair_sum<8>(su, K, sub, tid); break;
    }

    // ---- block reduction: warp shuffle tree, fixed order ----
#pragma unroll
    for (int d = 16; d > 0; d >>= 1)
        acc += __shfl_xor_sync(0xffffffffu, acc, d);
    if (lane == 0) warp_sum[wid] = acc;
    __syncthreads();
    if (tid == 0) {
        float bs = 0.f;
#pragma unroll
        for (int w = 0; w < 8; w++) bs += warp_sum[w];
        g_part[blockIdx.x] = bs;
        if (sub == 0) g_cnt[b] = K;
        __threadfence();
        int ticket = atomicAdd(&g_ticket, 1);
        s_last = (ticket == GRID - 1);
    }
    __syncthreads();

    // ---- last block finishes: reduce 296 partials in fixed order ----
    if (s_last) {
        __threadfence();
        float v = g_part[tid];
        if (tid + T < GRID) v += g_part[tid + T];
        red[tid] = v;
        __syncthreads();
#pragma unroll
        for (int sft = T / 2; sft > 0; sft >>= 1) {
            if (tid < sft) red[tid] += red[tid + sft];
            __syncthreads();
        }
        if (tid == 0) {
            double idx_num = 0.0;
#pragma unroll
            for (int bb = 0; bb < BB; bb++) {
                double k = (double)g_cnt[bb];
                idx_num += k * k;
            }
            out[0] = (float)((double)red[0] / idx_num);
            g_ticket = 0;    // reset for next graph replay
        }
    }
}

extern "C" void kernel_launch(void* const* d_in, const int* in_sizes, int n_in,
                              void* d_out, int out_size) {
    const float* gt  = (const float*)d_in[0];   // [8,48,2]
    const float* cs  = (const float*)d_in[1];   // [8,48,48]
    const float* thr = (const float*)d_in[2];   // [1]
    float* out = (float*)d_out;

    fused_kernel<<<GRID, T>>>(gt, cs, thr, out);
}

// round 6
// speedup vs baseline: 1.8750x; 1.1845x over previous
#include <cuda_runtime.h>
#include <math.h>

// Fixed problem shape: B=8, N=48, D=2
#define BB 8
#define NN 48
#define MM (NN * NN)          // 2304 candidate pair-vectors per batch
#define T 1024                // threads per block (1 block per batch)
#define H 1024                // angle bins over [0, pi)
#define HALF (H / 2)
#define PI_F 3.14159265358979f
#define INV_SCALE 9.313225746154785e-10f   // 2^-30
#define SCALE_F 1073741824.0f              // 2^30

// Scratch (allocations forbidden -> device globals)
__device__ float g_S[BB];
__device__ int   g_K[BB];
__device__ int   g_ticket = 0;

__global__ __launch_bounds__(T, 1)
void fused_kernel(const float* __restrict__ gt,
                  const float* __restrict__ cs,
                  const float* __restrict__ thr,
                  float* __restrict__ out) {
    const int b    = blockIdx.x;
    const int tid  = threadIdx.x;
    const int lane = tid & 31;
    const int wid  = tid >> 5;

    __shared__ float2 sg[NN];
    __shared__ unsigned long long hx[H], hy[H];   // fixed-point bin resultants
    __shared__ float2 P[H];                       // inclusive prefix of V
    __shared__ float2 wsum2[32];
    __shared__ float  warp_acc[32];
    __shared__ int    warp_cnt[32];

    // Zero histogram (T == H: one slot each)
    hx[tid] = 0ULL;
    hy[tid] = 0ULL;
    if (tid < NN) sg[tid] = ((const float2*)gt)[b * NN + tid];

    // Prefetch cs values (3 strided chunks) + threshold, overlapping smem init
    float s0 = cs[b * MM + tid];
    float s1 = cs[b * MM + T + tid];
    float s2 = (tid < MM - 2 * T) ? cs[b * MM + 2 * T + tid] : -1e30f;
    const float t = thr[0];
    __syncthreads();

    // ---- element phase: normalize, angle-bin, histogram ----
    int cnt = 0;
    float sv[3] = {s0, s1, s2};
#pragma unroll
    for (int k = 0; k < 3; k++) {
        int idx = k * T + tid;
        float ss = sv[k];
        bool valid = (k < 2) || (tid < MM - 2 * T);
        if (valid && ss >= t) {                 // ref: where(cos < thr, 0, cos)
            int i = idx / NN;
            int j = idx - i * NN;
            float vx = (sg[i].x - sg[j].x) * ss;
            float vy = (sg[i].y - sg[j].y) * ss;
            if (vx != 0.f || vy != 0.f) {
                // per-element eps as in reference: sqrt(vx^2+eps + vy^2+eps)
                float inv = rsqrtf(vx * vx + 1e-9f + vy * vy + 1e-9f);
                float ux = vx * inv, uy = vy * inv;
                // fold to upper half-plane: theta in [0, pi)
                if (uy < 0.f || (uy == 0.f && ux < 0.f)) { ux = -ux; uy = -uy; }
                // octant-reduced atan (max err ~1e-6 rad)
                float ax = fabsf(ux);
                float mx = fmaxf(ax, uy);
                float mn = fminf(ax, uy);
                float tt = __fdividef(mn, mx);
                float t2 = tt * tt;
                float p = tt * (0.99997726f + t2 * (-0.33262347f + t2 * (0.19354346f
                         + t2 * (-0.11643287f + t2 * (0.05265332f + t2 * (-0.01172120f))))));
                float th = (uy > ax) ? (1.57079632679f - p) : p;
                th = (ux < 0.f) ? (PI_F - th) : th;
                int bin = (int)(th * ((float)H / PI_F));
                bin = max(0, min(H - 1, bin));
                // exact, order-independent accumulation (deterministic)
                atomicAdd(&hx[bin], (unsigned long long)(long long)(ux * SCALE_F));
                atomicAdd(&hy[bin], (unsigned long long)(long long)(uy * SCALE_F));
                cnt++;
            }
        }
    }
    __syncthreads();

    // ---- per-bin resultant (float) ----
    float2 v;
    v.x = (float)(long long)hx[tid] * INV_SCALE;
    v.y = (float)(long long)hy[tid] * INV_SCALE;

    // ---- block-wide inclusive prefix sum of V over bins ----
    float2 sc = v;
#pragma unroll
    for (int d = 1; d < 32; d <<= 1) {
        float px = __shfl_up_sync(0xffffffffu, sc.x, d);
        float py = __shfl_up_sync(0xffffffffu, sc.y, d);
        if (lane >= d) { sc.x += px; sc.y += py; }
    }
    if (lane == 31) wsum2[wid] = sc;
    __syncthreads();
    if (wid == 0) {
        float2 w = wsum2[lane];
#pragma unroll
        for (int d = 1; d < 32; d <<= 1) {
            float px = __shfl_up_sync(0xffffffffu, w.x, d);
            float py = __shfl_up_sync(0xffffffffu, w.y, d);
            if (lane >= d) { w.x += px; w.y += py; }
        }
        wsum2[lane] = w;
    }
    __syncthreads();
    float2 base = (wid > 0) ? wsum2[wid - 1] : make_float2(0.f, 0.f);
    float2 Pin = make_float2(base.x + sc.x, base.y + sc.y);
    P[tid] = Pin;
    float2 Vtot = wsum2[31];
    __syncthreads();

    // ---- per-bin evaluation: A(p) = 2*arcsum - Vtot; acc = V_p . A(p) ----
    // positive-sign arc for bin p: bins q in [p-HALF+1, p+HALF-1] (clamped)
    float2 phi = (tid >= HALF) ? Vtot : P[tid + HALF - 1];
    float2 plo = (tid >= HALF) ? P[tid - HALF] : make_float2(0.f, 0.f);
    float Ax = 2.f * (phi.x - plo.x) - Vtot.x;
    float Ay = 2.f * (phi.y - plo.y) - Vtot.y;
    float acc = v.x * Ax + v.y * Ay;

    // ---- block reduction (fixed order -> deterministic) ----
#pragma unroll
    for (int d = 16; d > 0; d >>= 1) {
        acc += __shfl_xor_sync(0xffffffffu, acc, d);
        cnt += __shfl_xor_sync(0xffffffffu, cnt, d);
    }
    if (lane == 0) { warp_acc[wid] = acc; warp_cnt[wid] = cnt; }
    __syncthreads();
    if (tid == 0) {
        float S = 0.f;
        int K = 0;
#pragma unroll
        for (int w = 0; w < 32; w++) { S += warp_acc[w]; K += warp_cnt[w]; }
        g_S[b] = S;
        g_K[b] = K;
        __threadfence();
        int ticket = atomicAdd(&g_ticket, 1);
        if (ticket == BB - 1) {
            __threadfence();
            double total = 0.0, idx_num = 0.0;
#pragma unroll
            for (int bb = 0; bb < BB; bb++) {
                total += (double)g_S[bb];
                double k = (double)g_K[bb];
                idx_num += k * k;
            }
            out[0] = (float)(total / idx_num);
            g_ticket = 0;   // reset for next graph replay
        }
    }
}

extern "C" void kernel_launch(void* const* d_in, const int* in_sizes, int n_in,
                              void* d_out, int out_size) {
    const float* gt  = (const float*)d_in[0];   // [8,48,2]
    const float* cs  = (const float*)d_in[1];   // [8,48,48]
    const float* thr = (const float*)d_in[2];   // [1]
    float* out = (float*)d_out;

    fused_kernel<<<BB, T>>>(gt, cs, thr, out);
}